// round 14
// baseline (speedup 1.0000x reference)
#include <cuda_runtime.h>
#include <cstdint>

// Problem constants: B=2, N=65536, M=8192, K=32
// TOTAL_GIBS=64 (16 cy, 16 cone, 16 disk, 16 ellip), NUM_OBSERVERS=16
#define EPSV 1e-8f
#define LOG2E_F 1.4426950408889634f

constexpr int Bc = 2;
constexpr int Nc = 65536;
constexpr int Mc = 8192;
constexpr int Kc = 32;
constexpr int NQ = Bc * Mc;                 // 16384 queries
constexpr int WARPS_PER_BLOCK = 4;          // 128-thread blocks
constexpr int THREADS = WARPS_PER_BLOCK * 32;
constexpr int Q_PER_WARP = 2;
constexpr int Q_PER_BLOCK = WARPS_PER_BLOCK * Q_PER_WARP;   // 8
constexpr int GRID_BLOCKS = NQ / Q_PER_BLOCK;               // 2048
constexpr int RPAD = 68;                    // meanS row stride (words)
constexpr int KP = Kc + 1;                  // sPts row pad

__device__ __forceinline__ float ex2f(float x) {
    float r; asm("ex2.approx.ftz.f32 %0, %1;" : "=f"(r) : "f"(x)); return r;
}
__device__ __forceinline__ float sqrtaf(float x) {
    float r; asm("sqrt.approx.ftz.f32 %0, %1;" : "=f"(r) : "f"(x)); return r;
}

__global__ __launch_bounds__(THREADS, 14)   // 14 blocks/SM -> grid 2048 in ONE wave
void gib_kernel(const float* __restrict__ points,
                const float* __restrict__ q_coords,
                const int*   __restrict__ support_idxs,
                const float* __restrict__ cy_p,
                const float* __restrict__ cone_p,
                const float* __restrict__ disk_p,
                const float* __restrict__ ellip_p,
                const float* __restrict__ lambdas,
                float* __restrict__ out)
{
    // ONE record per (query,k), read warp-uniform: (r2, rx2, s, rz)
    __shared__ float4 sPts[WARPS_PER_BLOCK][Q_PER_WARP][KP];       // 4.2 KB
    // lamT4[g4*16 + j] = {lam[4g4..4g4+3][j]}/K
    __shared__ float4 lamT4[256];                                  // 4 KB
    __shared__ __align__(16) float meanS[Q_PER_BLOCK * RPAD];      // 2.2 KB

    const int tid   = threadIdx.x;
    const int lane  = tid & 31;
    const int wslot = tid >> 5;
    const int qbase = blockIdx.x * Q_PER_BLOCK;
    const int qA    = qbase + wslot * 2;

    // ---- cooperative packed-transposed lambda load (2 rows per thread) ----
    {
        const float invK = 1.f / (float)Kc;
        #pragma unroll
        for (int rep = 0; rep < 2; rep++) {
            int i  = tid + rep * THREADS;   // 0..255
            int g4 = i >> 4;                // 0..15
            int j  = i & 15;                // 0..15
            float4 v;
            v.x = lambdas[(4 * g4 + 0) * 16 + j] * invK;
            v.y = lambdas[(4 * g4 + 1) * 16 + j] * invK;
            v.z = lambdas[(4 * g4 + 2) * 16 + j] * invK;
            v.w = lambdas[(4 * g4 + 3) * 16 + j] * invK;
            lamT4[g4 * 16 + j] = v;
        }
    }

    // ---- per-lane gib constants (uniform instruction stream) ----
    // quad gib (g0=lane):  t = p1a*r2 + p1b*s + p2*rz + p3 ; contrib = 2^(-t*t)
    // lin gib (g1=lane+32): a1 = e1*rx2 + e2*r2 + e3*rz2 ; contrib = 2^a1
    float p1a, p1b, p2, p3, e1, e2, e3;
    if (lane < 16) {
        float a  = cy_p[lane * 2 + 0];
        float sg = cy_p[lane * 2 + 1];
        float s0 = sqrtf(LOG2E_F / (2.f * sg * sg + EPSV));
        p1a = s0; p1b = 0.f; p2 = 0.f; p3 = -s0 * a * a;
        float d0 = disk_p[lane * 2 + 0];
        float d1 = disk_p[lane * 2 + 1];
        e1 = 0.f;
        e2 = -LOG2E_F / (d0 * d0 + EPSV);
        e3 = -LOG2E_F / (d1 * d1 + EPSV);
    } else {
        int j = lane - 16;
        float a  = cone_p[j * 2 + 0];
        float sg = cone_p[j * 2 + 1];
        float s0 = sqrtf(LOG2E_F / (2.f * sg * sg + EPSV));
        p1a = 0.f; p1b = s0; p2 = -s0 * a; p3 = 0.f;
        float x0 = ellip_p[j * 3 + 0];
        float x1 = ellip_p[j * 3 + 1];
        float x2 = ellip_p[j * 3 + 2];
        float qx = -LOG2E_F / (x0 * x0 + EPSV);
        float qy = -LOG2E_F / (x1 * x1 + EPSV);
        e1 = qx - qy;                       // on rx2
        e2 = qy;                            // on r2
        e3 = -LOG2E_F / (x2 * x2 + EPSV);   // on rz2
    }

    // ---- gather: lane k loads support point k (2x LDG.64 parity select) ----
    #pragma unroll
    for (int qq = 0; qq < Q_PER_WARP; qq++) {
        int q = qA + qq;
        const float* qc = q_coords + q * 3;
        float qx = __ldg(qc + 0);
        float qy = __ldg(qc + 1);
        float qz = __ldg(qc + 2);
        int   idx = __ldg(support_idxs + q * Kc + lane);
        int   b   = q >> 13;                          // q / Mc
        unsigned pidx = ((unsigned)b << 16) + (unsigned)idx;   // b*Nc + idx
        unsigned offb = pidx * 12u;                   // parity select on idx&1
        const char* pb = (const char*)points + (offb & ~7u);
        float2 lo = __ldg((const float2*)pb);
        float2 hi = __ldg((const float2*)(pb + 8));
        bool odd = (idx & 1);
        float px = odd ? lo.y : lo.x;
        float py = odd ? hi.x : lo.y;
        float pz = odd ? hi.y : hi.x;
        float rx = px - qx;
        float ry = py - qy;
        float rz = pz - qz;
        float rx2 = rx * rx;
        float r2  = fmaf(ry, ry, rx2);
        float s   = sqrtaf(r2 + EPSV);
        sPts[wslot][qq][lane] = make_float4(r2, rx2, s, rz);
    }
    __syncwarp();

    const float4* vA = sPts[wslot][0];
    const float4* vB = sPts[wslot][1];

    float acc0A = 0.f, acc1A = 0.f, acc0B = 0.f, acc1B = 0.f;
    #pragma unroll 4
    for (int k = 0; k < Kc; k++) {
        float4 a = vA[k];                 // warp-uniform LDS.128 -> broadcast
        float4 b = vB[k];

        float tA = fmaf(p1a, a.x, fmaf(p1b, a.z, fmaf(p2, a.w, p3)));
        float tB = fmaf(p1a, b.x, fmaf(p1b, b.z, fmaf(p2, b.w, p3)));
        float zA = a.w * a.w;
        float zB = b.w * b.w;
        float aA = fmaf(e1, a.y, fmaf(e2, a.x, e3 * zA));
        float aB = fmaf(e1, b.y, fmaf(e2, b.x, e3 * zB));

        acc0A += ex2f(-tA * tA);
        acc0B += ex2f(-tB * tB);
        acc1A += ex2f(aA);
        acc1B += ex2f(aB);
    }

    // publish the 64 gib means for both queries
    {
        int qqA = wslot * 2, qqB = qqA + 1;
        meanS[qqA * RPAD + lane]      = acc0A;
        meanS[qqA * RPAD + lane + 32] = acc1A;
        meanS[qqB * RPAD + lane]      = acc0B;
        meanS[qqB * RPAD + lane + 32] = acc1B;
    }
    __syncthreads();

    // ---- block-cooperative epilogue: 8 queries x 16 observers = 128 threads ----
    {
        int qq = tid >> 4;
        int j  = tid & 15;
        const float4* mrow = reinterpret_cast<const float4*>(&meanS[qq * RPAD]);
        float acc = 0.f;
        #pragma unroll
        for (int g4 = 0; g4 < 16; g4++) {
            float4 m = mrow[g4];
            float4 l = lamT4[g4 * 16 + j];
            acc += m.x * l.x + m.y * l.y + m.z * l.z + m.w * l.w;
        }
        out[(size_t)(qbase + qq) * 16 + j] = acc;   // fully coalesced
    }
}

extern "C" void kernel_launch(void* const* d_in, const int* in_sizes, int n_in,
                              void* d_out, int out_size)
{
    // metadata order: points, q_coords, support_idxs, mc_points (unused),
    //                 cy_params, cone_params, disk_params, ellip_params, lambdas
    const float* points       = (const float*)d_in[0];
    const float* q_coords     = (const float*)d_in[1];
    const int*   support_idxs = (const int*)  d_in[2];
    const float* cy_params    = (const float*)d_in[4];
    const float* cone_params  = (const float*)d_in[5];
    const float* disk_params  = (const float*)d_in[6];
    const float* ellip_params = (const float*)d_in[7];
    const float* lambdas      = (const float*)d_in[8];
    float* out = (float*)d_out;

    gib_kernel<<<GRID_BLOCKS, THREADS>>>(points, q_coords, support_idxs,
                                         cy_params, cone_params, disk_params,
                                         ellip_params, lambdas, out);
}

// round 15
// speedup vs baseline: 1.1194x; 1.1194x over previous
#include <cuda_runtime.h>
#include <cstdint>

// Problem constants: B=2, N=65536, M=8192, K=32
// TOTAL_GIBS=64 (16 cy, 16 cone, 16 disk, 16 ellip), NUM_OBSERVERS=16
#define EPSV 1e-8f
#define LOG2E_F 1.4426950408889634f

constexpr int Bc = 2;
constexpr int Nc = 65536;
constexpr int Mc = 8192;
constexpr int Kc = 32;
constexpr int NQ = Bc * Mc;                 // 16384 queries
constexpr int WARPS_PER_BLOCK = 4;          // 128-thread blocks
constexpr int THREADS = WARPS_PER_BLOCK * 32;
constexpr int Q_PER_WARP = 4;
constexpr int Q_PER_BLOCK = WARPS_PER_BLOCK * Q_PER_WARP;   // 16
constexpr int GRID_BLOCKS = NQ / Q_PER_BLOCK;               // 1024 -> single wave
constexpr int RPAD = 68;                    // meanS row stride (words)
constexpr int KP = Kc + 1;                  // sPts row pad

__device__ __forceinline__ float ex2f(float x) {
    float r; asm("ex2.approx.ftz.f32 %0, %1;" : "=f"(r) : "f"(x)); return r;
}
__device__ __forceinline__ float sqrtaf(float x) {
    float r; asm("sqrt.approx.ftz.f32 %0, %1;" : "=f"(r) : "f"(x)); return r;
}

__global__ __launch_bounds__(THREADS, 9)    // reg cap 56
void gib_kernel(const float* __restrict__ points,
                const float* __restrict__ q_coords,
                const int*   __restrict__ support_idxs,
                const float* __restrict__ cy_p,
                const float* __restrict__ cone_p,
                const float* __restrict__ disk_p,
                const float* __restrict__ ellip_p,
                const float* __restrict__ lambdas,
                float* __restrict__ out)
{
    // ONE record per (query,k), read warp-uniform: (r2, rx2, s, rz)
    __shared__ float4 sPts[WARPS_PER_BLOCK][Q_PER_WARP][KP];       // 8.4 KB
    // lamT4[g4*16 + j] = {lam[4g4..4g4+3][j]}/K
    __shared__ float4 lamT4[256];                                  // 4 KB
    __shared__ __align__(16) float meanS[Q_PER_BLOCK * RPAD];      // 4.3 KB

    const int tid   = threadIdx.x;
    const int lane  = tid & 31;
    const int wslot = tid >> 5;
    const int qbase = blockIdx.x * Q_PER_BLOCK;
    const int qA    = qbase + wslot * Q_PER_WARP;

    // ---- cooperative packed-transposed lambda load (2 rows per thread) ----
    {
        const float invK = 1.f / (float)Kc;
        #pragma unroll
        for (int rep = 0; rep < 2; rep++) {
            int i  = tid + rep * THREADS;   // 0..255
            int g4 = i >> 4;                // 0..15
            int j  = i & 15;                // 0..15
            float4 v;
            v.x = lambdas[(4 * g4 + 0) * 16 + j] * invK;
            v.y = lambdas[(4 * g4 + 1) * 16 + j] * invK;
            v.z = lambdas[(4 * g4 + 2) * 16 + j] * invK;
            v.w = lambdas[(4 * g4 + 3) * 16 + j] * invK;
            lamT4[g4 * 16 + j] = v;
        }
    }

    // ---- per-lane gib constants (uniform instruction stream) ----
    // quad gib (g0=lane):  t = p1a*r2 + p1b*s + p2*rz + p3 ; contrib = 2^(-t*t)
    // lin gib (g1=lane+32): a1 = e1*rx2 + e2*r2 + e3*rz2 ; contrib = 2^a1
    float p1a, p1b, p2, p3, e1, e2, e3;
    if (lane < 16) {
        float a  = cy_p[lane * 2 + 0];
        float sg = cy_p[lane * 2 + 1];
        float s0 = sqrtf(LOG2E_F / (2.f * sg * sg + EPSV));
        p1a = s0; p1b = 0.f; p2 = 0.f; p3 = -s0 * a * a;
        float d0 = disk_p[lane * 2 + 0];
        float d1 = disk_p[lane * 2 + 1];
        e1 = 0.f;
        e2 = -LOG2E_F / (d0 * d0 + EPSV);
        e3 = -LOG2E_F / (d1 * d1 + EPSV);
    } else {
        int j = lane - 16;
        float a  = cone_p[j * 2 + 0];
        float sg = cone_p[j * 2 + 1];
        float s0 = sqrtf(LOG2E_F / (2.f * sg * sg + EPSV));
        p1a = 0.f; p1b = s0; p2 = -s0 * a; p3 = 0.f;
        float x0 = ellip_p[j * 3 + 0];
        float x1 = ellip_p[j * 3 + 1];
        float x2 = ellip_p[j * 3 + 2];
        float qx = -LOG2E_F / (x0 * x0 + EPSV);
        float qy = -LOG2E_F / (x1 * x1 + EPSV);
        e1 = qx - qy;                       // on rx2
        e2 = qy;                            // on r2
        e3 = -LOG2E_F / (x2 * x2 + EPSV);   // on rz2
    }

    // ---- gather: lane k loads support point k (2x LDG.64 parity select) ----
    #pragma unroll
    for (int qq = 0; qq < Q_PER_WARP; qq++) {
        int q = qA + qq;
        const float* qc = q_coords + q * 3;
        float qx = __ldg(qc + 0);
        float qy = __ldg(qc + 1);
        float qz = __ldg(qc + 2);
        int   idx = __ldg(support_idxs + q * Kc + lane);
        int   b   = q >> 13;                          // q / Mc
        unsigned pidx = ((unsigned)b << 16) + (unsigned)idx;   // b*Nc + idx
        unsigned offb = pidx * 12u;                   // parity select on idx&1
        const char* pb = (const char*)points + (offb & ~7u);
        float2 lo = __ldg((const float2*)pb);
        float2 hi = __ldg((const float2*)(pb + 8));
        bool odd = (idx & 1);
        float px = odd ? lo.y : lo.x;
        float py = odd ? hi.x : lo.y;
        float pz = odd ? hi.y : hi.x;
        float rx = px - qx;
        float ry = py - qy;
        float rz = pz - qz;
        float rx2 = rx * rx;
        float r2  = fmaf(ry, ry, rx2);
        float s   = sqrtaf(r2 + EPSV);
        sPts[wslot][qq][lane] = make_float4(r2, rx2, s, rz);
    }
    __syncwarp();

    const float4* v0 = sPts[wslot][0];
    const float4* v1 = sPts[wslot][1];
    const float4* v2 = sPts[wslot][2];
    const float4* v3 = sPts[wslot][3];

    float acc0[Q_PER_WARP] = {0.f, 0.f, 0.f, 0.f};
    float acc1[Q_PER_WARP] = {0.f, 0.f, 0.f, 0.f};

    #pragma unroll 4
    for (int k = 0; k < Kc; k++) {
        float4 a = v0[k];                 // 4 independent chains per iteration
        float4 b = v1[k];
        float4 c = v2[k];
        float4 d = v3[k];

        float tA = fmaf(p1a, a.x, fmaf(p1b, a.z, fmaf(p2, a.w, p3)));
        float tB = fmaf(p1a, b.x, fmaf(p1b, b.z, fmaf(p2, b.w, p3)));
        float tC = fmaf(p1a, c.x, fmaf(p1b, c.z, fmaf(p2, c.w, p3)));
        float tD = fmaf(p1a, d.x, fmaf(p1b, d.z, fmaf(p2, d.w, p3)));

        float uA = fmaf(e1, a.y, fmaf(e2, a.x, e3 * (a.w * a.w)));
        float uB = fmaf(e1, b.y, fmaf(e2, b.x, e3 * (b.w * b.w)));
        float uC = fmaf(e1, c.y, fmaf(e2, c.x, e3 * (c.w * c.w)));
        float uD = fmaf(e1, d.y, fmaf(e2, d.x, e3 * (d.w * d.w)));

        acc0[0] += ex2f(-tA * tA);
        acc0[1] += ex2f(-tB * tB);
        acc0[2] += ex2f(-tC * tC);
        acc0[3] += ex2f(-tD * tD);
        acc1[0] += ex2f(uA);
        acc1[1] += ex2f(uB);
        acc1[2] += ex2f(uC);
        acc1[3] += ex2f(uD);
    }

    // publish the 64 gib means for all 4 queries
    #pragma unroll
    for (int qq = 0; qq < Q_PER_WARP; qq++) {
        int row = (wslot * Q_PER_WARP + qq) * RPAD;
        meanS[row + lane]      = acc0[qq];
        meanS[row + lane + 32] = acc1[qq];
    }
    __syncthreads();

    // ---- block-cooperative epilogue: 16 queries x 16 observers, 2 per thread ----
    #pragma unroll
    for (int rep = 0; rep < 2; rep++) {
        int e  = tid + rep * THREADS;      // 0..255
        int qq = e >> 4;
        int j  = e & 15;
        const float4* mrow = reinterpret_cast<const float4*>(&meanS[qq * RPAD]);
        float acc = 0.f;
        #pragma unroll
        for (int g4 = 0; g4 < 16; g4++) {
            float4 m = mrow[g4];
            float4 l = lamT4[g4 * 16 + j];
            acc += m.x * l.x + m.y * l.y + m.z * l.z + m.w * l.w;
        }
        out[(size_t)(qbase + qq) * 16 + j] = acc;   // fully coalesced
    }
}

extern "C" void kernel_launch(void* const* d_in, const int* in_sizes, int n_in,
                              void* d_out, int out_size)
{
    // metadata order: points, q_coords, support_idxs, mc_points (unused),
    //                 cy_params, cone_params, disk_params, ellip_params, lambdas
    const float* points       = (const float*)d_in[0];
    const float* q_coords     = (const float*)d_in[1];
    const int*   support_idxs = (const int*)  d_in[2];
    const float* cy_params    = (const float*)d_in[4];
    const float* cone_params  = (const float*)d_in[5];
    const float* disk_params  = (const float*)d_in[6];
    const float* ellip_params = (const float*)d_in[7];
    const float* lambdas      = (const float*)d_in[8];
    float* out = (float*)d_out;

    gib_kernel<<<GRID_BLOCKS, THREADS>>>(points, q_coords, support_idxs,
                                         cy_params, cone_params, disk_params,
                                         ellip_params, lambdas, out);
}

// round 16
// speedup vs baseline: 1.1364x; 1.0152x over previous
#include <cuda_runtime.h>
#include <cstdint>

// Problem constants: B=2, N=65536, M=8192, K=32
// TOTAL_GIBS=64 (16 cy, 16 cone, 16 disk, 16 ellip), NUM_OBSERVERS=16
#define EPSV 1e-8f
#define LOG2E_F 1.4426950408889634f

constexpr int Bc = 2;
constexpr int Nc = 65536;
constexpr int Mc = 8192;
constexpr int Kc = 32;
constexpr int NQ = Bc * Mc;                 // 16384 queries
constexpr int WARPS_PER_BLOCK = 4;          // 128-thread blocks
constexpr int THREADS = WARPS_PER_BLOCK * 32;
constexpr int Q_PER_WARP = 4;
constexpr int Q_PER_BLOCK = WARPS_PER_BLOCK * Q_PER_WARP;   // 16
constexpr int GRID_BLOCKS = NQ / Q_PER_BLOCK;               // 1024 -> single wave
constexpr int RPAD = 68;                    // meanS row stride (words)
constexpr int KP = Kc + 1;                  // sPts row pad

__device__ __forceinline__ float ex2f(float x) {
    float r; asm("ex2.approx.ftz.f32 %0, %1;" : "=f"(r) : "f"(x)); return r;
}
__device__ __forceinline__ float sqrtaf(float x) {
    float r; asm("sqrt.approx.ftz.f32 %0, %1;" : "=f"(r) : "f"(x)); return r;
}

__global__ __launch_bounds__(THREADS, 8)    // reg cap 64; 8 blocks/SM >= 6.9 needed
void gib_kernel(const float* __restrict__ points,
                const float* __restrict__ q_coords,
                const int*   __restrict__ support_idxs,
                const float* __restrict__ cy_p,
                const float* __restrict__ cone_p,
                const float* __restrict__ disk_p,
                const float* __restrict__ ellip_p,
                const float* __restrict__ lambdas,
                float* __restrict__ out)
{
    // ONE record per (query,k), read warp-uniform: (r2, rx2, s, rz)
    __shared__ float4 sPts[WARPS_PER_BLOCK][Q_PER_WARP][KP];       // 8.4 KB
    // lamT4[g4*16 + j] = {lam[4g4..4g4+3][j]}/K
    __shared__ float4 lamT4[256];                                  // 4 KB
    __shared__ __align__(16) float meanS[Q_PER_BLOCK * RPAD];      // 4.3 KB

    const int tid   = threadIdx.x;
    const int lane  = tid & 31;
    const int wslot = tid >> 5;
    const int qbase = blockIdx.x * Q_PER_BLOCK;
    const int qA    = qbase + wslot * Q_PER_WARP;

    // ---- cooperative packed-transposed lambda load (2 rows per thread) ----
    {
        const float invK = 1.f / (float)Kc;
        #pragma unroll
        for (int rep = 0; rep < 2; rep++) {
            int i  = tid + rep * THREADS;   // 0..255
            int g4 = i >> 4;                // 0..15
            int j  = i & 15;                // 0..15
            float4 v;
            v.x = lambdas[(4 * g4 + 0) * 16 + j] * invK;
            v.y = lambdas[(4 * g4 + 1) * 16 + j] * invK;
            v.z = lambdas[(4 * g4 + 2) * 16 + j] * invK;
            v.w = lambdas[(4 * g4 + 3) * 16 + j] * invK;
            lamT4[g4 * 16 + j] = v;
        }
    }

    // ---- per-lane gib constants (uniform instruction stream) ----
    // quad gib (g0=lane):  t = p1a*r2 + p1b*s + p2*rz + p3 ; contrib = 2^(-t*t)
    // lin gib (g1=lane+32): a1 = e1*rx2 + e2*r2 + e3*rz2 ; contrib = 2^a1
    float p1a, p1b, p2, p3, e1, e2, e3;
    if (lane < 16) {
        float a  = cy_p[lane * 2 + 0];
        float sg = cy_p[lane * 2 + 1];
        float s0 = sqrtf(LOG2E_F / (2.f * sg * sg + EPSV));
        p1a = s0; p1b = 0.f; p2 = 0.f; p3 = -s0 * a * a;
        float d0 = disk_p[lane * 2 + 0];
        float d1 = disk_p[lane * 2 + 1];
        e1 = 0.f;
        e2 = -LOG2E_F / (d0 * d0 + EPSV);
        e3 = -LOG2E_F / (d1 * d1 + EPSV);
    } else {
        int j = lane - 16;
        float a  = cone_p[j * 2 + 0];
        float sg = cone_p[j * 2 + 1];
        float s0 = sqrtf(LOG2E_F / (2.f * sg * sg + EPSV));
        p1a = 0.f; p1b = s0; p2 = -s0 * a; p3 = 0.f;
        float x0 = ellip_p[j * 3 + 0];
        float x1 = ellip_p[j * 3 + 1];
        float x2 = ellip_p[j * 3 + 2];
        float qx = -LOG2E_F / (x0 * x0 + EPSV);
        float qy = -LOG2E_F / (x1 * x1 + EPSV);
        e1 = qx - qy;                       // on rx2
        e2 = qy;                            // on r2
        e3 = -LOG2E_F / (x2 * x2 + EPSV);   // on rz2
    }

    // ---- gather: lane k loads support point k (2x LDG.64 parity select) ----
    #pragma unroll
    for (int qq = 0; qq < Q_PER_WARP; qq++) {
        int q = qA + qq;
        const float* qc = q_coords + q * 3;
        float qx = __ldg(qc + 0);
        float qy = __ldg(qc + 1);
        float qz = __ldg(qc + 2);
        int   idx = __ldg(support_idxs + q * Kc + lane);
        int   b   = q >> 13;                          // q / Mc
        unsigned pidx = ((unsigned)b << 16) + (unsigned)idx;   // b*Nc + idx
        unsigned offb = pidx * 12u;                   // parity select on idx&1
        const char* pb = (const char*)points + (offb & ~7u);
        float2 lo = __ldg((const float2*)pb);
        float2 hi = __ldg((const float2*)(pb + 8));
        bool odd = (idx & 1);
        float px = odd ? lo.y : lo.x;
        float py = odd ? hi.x : lo.y;
        float pz = odd ? hi.y : hi.x;
        float rx = px - qx;
        float ry = py - qy;
        float rz = pz - qz;
        float rx2 = rx * rx;
        float r2  = fmaf(ry, ry, rx2);
        float s   = sqrtaf(r2 + EPSV);
        sPts[wslot][qq][lane] = make_float4(r2, rx2, s, rz);
    }
    __syncwarp();

    const float4* v0 = sPts[wslot][0];
    const float4* v1 = sPts[wslot][1];
    const float4* v2 = sPts[wslot][2];
    const float4* v3 = sPts[wslot][3];

    float acc0[Q_PER_WARP] = {0.f, 0.f, 0.f, 0.f};
    float acc1[Q_PER_WARP] = {0.f, 0.f, 0.f, 0.f};

    #pragma unroll 8
    for (int k = 0; k < Kc; k++) {
        float4 a = v0[k];                 // 4 independent chains per iteration
        float4 b = v1[k];
        float4 c = v2[k];
        float4 d = v3[k];

        float tA = fmaf(p1a, a.x, fmaf(p1b, a.z, fmaf(p2, a.w, p3)));
        float tB = fmaf(p1a, b.x, fmaf(p1b, b.z, fmaf(p2, b.w, p3)));
        float tC = fmaf(p1a, c.x, fmaf(p1b, c.z, fmaf(p2, c.w, p3)));
        float tD = fmaf(p1a, d.x, fmaf(p1b, d.z, fmaf(p2, d.w, p3)));

        float uA = fmaf(e1, a.y, fmaf(e2, a.x, e3 * (a.w * a.w)));
        float uB = fmaf(e1, b.y, fmaf(e2, b.x, e3 * (b.w * b.w)));
        float uC = fmaf(e1, c.y, fmaf(e2, c.x, e3 * (c.w * c.w)));
        float uD = fmaf(e1, d.y, fmaf(e2, d.x, e3 * (d.w * d.w)));

        acc0[0] += ex2f(-tA * tA);
        acc0[1] += ex2f(-tB * tB);
        acc0[2] += ex2f(-tC * tC);
        acc0[3] += ex2f(-tD * tD);
        acc1[0] += ex2f(uA);
        acc1[1] += ex2f(uB);
        acc1[2] += ex2f(uC);
        acc1[3] += ex2f(uD);
    }

    // publish the 64 gib means for all 4 queries
    #pragma unroll
    for (int qq = 0; qq < Q_PER_WARP; qq++) {
        int row = (wslot * Q_PER_WARP + qq) * RPAD;
        meanS[row + lane]      = acc0[qq];
        meanS[row + lane + 32] = acc1[qq];
    }
    __syncthreads();

    // ---- block-cooperative epilogue: 16 queries x 16 observers, 2 per thread ----
    #pragma unroll
    for (int rep = 0; rep < 2; rep++) {
        int e  = tid + rep * THREADS;      // 0..255
        int qq = e >> 4;
        int j  = e & 15;
        const float4* mrow = reinterpret_cast<const float4*>(&meanS[qq * RPAD]);
        float acc = 0.f;
        #pragma unroll
        for (int g4 = 0; g4 < 16; g4++) {
            float4 m = mrow[g4];
            float4 l = lamT4[g4 * 16 + j];
            acc += m.x * l.x + m.y * l.y + m.z * l.z + m.w * l.w;
        }
        out[(size_t)(qbase + qq) * 16 + j] = acc;   // fully coalesced
    }
}

extern "C" void kernel_launch(void* const* d_in, const int* in_sizes, int n_in,
                              void* d_out, int out_size)
{
    // metadata order: points, q_coords, support_idxs, mc_points (unused),
    //                 cy_params, cone_params, disk_params, ellip_params, lambdas
    const float* points       = (const float*)d_in[0];
    const float* q_coords     = (const float*)d_in[1];
    const int*   support_idxs = (const int*)  d_in[2];
    const float* cy_params    = (const float*)d_in[4];
    const float* cone_params  = (const float*)d_in[5];
    const float* disk_params  = (const float*)d_in[6];
    const float* ellip_params = (const float*)d_in[7];
    const float* lambdas      = (const float*)d_in[8];
    float* out = (float*)d_out;

    gib_kernel<<<GRID_BLOCKS, THREADS>>>(points, q_coords, support_idxs,
                                         cy_params, cone_params, disk_params,
                                         ellip_params, lambdas, out);
}